// round 8
// baseline (speedup 1.0000x reference)
#include <cuda_runtime.h>
#include <cuda_fp16.h>
#include <cstdint>

// Problem dims
#define IN_F   4096
#define OUT_F  11008
#define MROWS  2048
#define NUMEL  (IN_F * OUT_F)        // 45,088,768
#define PACKED_N (NUMEL / 2)         // 22,544,384
#define PROW   (IN_F / 2)            // 2048 packed ints per W row
#define SCALES_PER_ROW (IN_F / 64)   // 64 absmax scales per W row

// GEMM tiling
#define BM 256
#define BN 128
#define BK 64
#define KCHUNKS (IN_F / BK)          // 64

// smem rings
#define NSA 4                        // A stages (prefetch distance 3)
#define NSP 3                        // packed-B stages
#define A_ST 32768                   // 256 rows x 128B
#define P_ST 16384                   // 128 rows x 128B (32 int32/row)
#define B16_ST 16384                 // 128 rows x 128B fp16
#define P_OFF   (NSA * A_ST)                 // 131072
#define B16_OFF (P_OFF + NSP * P_ST)         // 180224
#define LUT_OFF (B16_OFF + 2 * B16_ST)       // 212992
#define SMEM_BYTES (LUT_OFF + 2048)          // 215040

#define CVT_BLOCKS ((MROWS * IN_F / 4) / 256)   // 8192

// Scratch (device global; no allocation allowed)
__device__ __half g_X[MROWS * IN_F];   // fp16 x

__constant__ float c_nf4[16] = {
    -1.0f, -0.6961928009986877f, -0.5250730514526367f, -0.39491748809814453f,
    -0.28444138169288635f, -0.18477343022823334f, -0.09105003625154495f, 0.0f,
    0.07958029955625534f, 0.16093020141124725f, 0.24611230194568634f,
    0.33791524171829224f, 0.44070982933044434f, 0.5626170039176941f,
    0.7229568362236023f, 1.0f};

// ---------------------------------------------------------------------------
// prep: x fp32 -> fp16 only (W dequant is fused into the GEMM)
// ---------------------------------------------------------------------------
__global__ void cvt_kernel(const float* __restrict__ x) {
    int i = blockIdx.x * blockDim.x + threadIdx.x;        // handles 4 floats
    float4 v = reinterpret_cast<const float4*>(x)[i];
    __half2* o = reinterpret_cast<__half2*>(g_X);
    o[2 * i]     = __floats2half2_rn(v.x, v.y);
    o[2 * i + 1] = __floats2half2_rn(v.z, v.w);
}

// ---------------------------------------------------------------------------
// PTX helpers
// ---------------------------------------------------------------------------
__device__ __forceinline__ uint32_t smem_u32(const void* p) {
    uint32_t a;
    asm("{ .reg .u64 t; cvta.to.shared.u64 t, %1; cvt.u32.u64 %0, t; }"
        : "=r"(a) : "l"(p));
    return a;
}

__device__ __forceinline__ void cp16(uint32_t saddr, const void* gaddr) {
    asm volatile("cp.async.cg.shared.global [%0], [%1], 16;"
                 :: "r"(saddr), "l"(gaddr));
}

__device__ __forceinline__ void ldm_x4(uint32_t* r, uint32_t addr) {
    asm volatile("ldmatrix.sync.aligned.m8n8.x4.shared.b16 {%0,%1,%2,%3}, [%4];"
                 : "=r"(r[0]), "=r"(r[1]), "=r"(r[2]), "=r"(r[3]) : "r"(addr));
}

__device__ __forceinline__ void mma16816(float* c, const uint32_t* a,
                                         uint32_t b0, uint32_t b1) {
    asm volatile(
        "mma.sync.aligned.m16n8k16.row.col.f32.f16.f16.f32 "
        "{%0,%1,%2,%3}, {%4,%5,%6,%7}, {%8,%9}, {%0,%1,%2,%3};"
        : "+f"(c[0]), "+f"(c[1]), "+f"(c[2]), "+f"(c[3])
        : "r"(a[0]), "r"(a[1]), "r"(a[2]), "r"(a[3]), "r"(b0), "r"(b1));
}

__device__ __forceinline__ void lds128(int* v, uint32_t a) {
    asm volatile("ld.shared.v4.b32 {%0,%1,%2,%3}, [%4];"
                 : "=r"(v[0]), "=r"(v[1]), "=r"(v[2]), "=r"(v[3]) : "r"(a));
}

__device__ __forceinline__ void sts128(uint32_t a, const uint32_t* v) {
    asm volatile("st.shared.v4.b32 [%0], {%1,%2,%3,%4};"
                 :: "r"(a), "r"(v[0]), "r"(v[1]), "r"(v[2]), "r"(v[3])
                 : "memory");
}

// ---------------------------------------------------------------------------
// Fused GEMM: out[256,128] tile = A[256,K] * dequant(B)[128,K]^T + bias.
// A fp16 from g_X (cp.async, 4-stage ring). B loaded as PACKED int32 codes
// (cp.async, 3-stage ring, same 128B-row SW128 geometry), NF4-dequantized
// in-kernel via 32x-replicated smem LUT into a 2-stage fp16 ring.
// f32 HMMA accumulation (round-5 math: rel_err 2.87e-4, gemm 579us).
// 512 threads = 16 warps (4m x 4n), warp tile 64x32, one sync per chunk.
// ---------------------------------------------------------------------------
__global__ void __launch_bounds__(512, 1)
gemm_kernel(const int* __restrict__ packed, const float* __restrict__ absmax,
            const float* __restrict__ bias, float* __restrict__ out) {
    extern __shared__ char smem[];
    const uint32_t sb = smem_u32(smem);
    float* lutp = reinterpret_cast<float*>(smem + LUT_OFF);
    const int tid = threadIdx.x;
    const int wid = tid >> 5;
    const int lane = tid & 31;
    const int warp_m = wid >> 2;          // 0..3 (64-row blocks)
    const int warp_n = wid & 3;           // 0..3 (32-col blocks)
    const int row0 = blockIdx.y * BM;
    const int col0 = blockIdx.x * BN;

    // 32x-replicated NF4 LUT: lut[code*32 + lane] -> bank == lane
    lutp[tid] = c_nf4[tid >> 5];          // 512 entries exactly

    const __half* Ab = g_X + (size_t)row0 * IN_F;
    const int* Pb = packed + (size_t)col0 * PROW;

    // cp.async chunk c: A fp16 into stage c%4, packed B into stage c%3
    auto issue = [&](int c) {
        const int kc = c * BK;
        const uint32_t abase = sb + (c & 3) * A_ST;
#pragma unroll
        for (int i = 0; i < 4; i++) {     // A: 2048 16B units / 512 thr
            int u = tid + (i << 9);
            int r = u >> 3, sg = u & 7;
            uint32_t bo = (uint32_t)((r << 7) + (sg << 4));
            uint32_t sw = bo ^ ((bo >> 3) & 0x70);
            cp16(abase + sw, Ab + (size_t)r * IN_F + kc + sg * 8);
        }
        const uint32_t pbase = sb + P_OFF + (c % NSP) * P_ST;
        const int pk = c * (BK / 2);      // packed ints offset within row
#pragma unroll
        for (int i = 0; i < 2; i++) {     // packed: 1024 16B units / 512 thr
            int u = tid + (i << 9);
            int r = u >> 3, sg = u & 7;
            uint32_t bo = (uint32_t)((r << 7) + (sg << 4));
            uint32_t sw = bo ^ ((bo >> 3) & 0x70);
            cp16(pbase + sw, Pb + (size_t)r * PROW + pk + sg * 4);
        }
    };

    // dequant chunk c: packed stage c%3 -> fp16 stage c&1.
    // thread t: row r = t>>2, quarter q = t&3 (8 ints -> 16 fp16 = 32B)
    const int dq_r = tid >> 2, dq_q = tid & 3;
    const uint32_t dq_bo0 = (uint32_t)((dq_r << 7) + (dq_q << 5));
    const uint32_t dq_bo1 = dq_bo0 + 16;
    const uint32_t dq_sw0 = dq_bo0 ^ ((dq_bo0 >> 3) & 0x70);
    const uint32_t dq_sw1 = dq_bo1 ^ ((dq_bo1 >> 3) & 0x70);
    auto dequant = [&](int c, float s) {
        const uint32_t pbase = sb + P_OFF + (c % NSP) * P_ST;
        const uint32_t dbase = sb + B16_OFF + (c & 1) * B16_ST;
        int v[8];
        lds128(v + 0, pbase + dq_sw0);
        lds128(v + 4, pbase + dq_sw1);
        uint32_t h[8];
#pragma unroll
        for (int j = 0; j < 8; j++) {
            float whi = lutp[((v[j] >> 4) & 0xF) * 32 + lane] * s;
            float wlo = lutp[(v[j] & 0xF) * 32 + lane] * s;
            __half2 p = __floats2half2_rn(whi, wlo);
            h[j] = *reinterpret_cast<uint32_t*>(&p);
        }
        sts128(dbase + dq_sw0, h + 0);
        sts128(dbase + dq_sw1, h + 4);
    };
    // absmax scales for this thread's dequant row: one per K64 chunk
    const float* amrow = absmax + (size_t)(col0 + dq_r) * SCALES_PER_ROW;

    // per-thread ldmatrix lane addressing (SW128; validated round 2)
    const int grp = lane >> 3, lr = lane & 7;
    const uint32_t xorv = (uint32_t)(lr << 4);
    const uint32_t laneoff =
        (uint32_t)((((grp & 1) << 3) + lr) << 7) + (uint32_t)((grp >> 1) << 4);
    const uint32_t aoff0 = (uint32_t)((warp_m * 64) << 7) + laneoff;
    const uint32_t boff0 = (uint32_t)((warp_n * 32) << 7) + laneoff;

    float C[4][4][4];
#pragma unroll
    for (int a = 0; a < 4; a++)
#pragma unroll
        for (int b = 0; b < 4; b++)
#pragma unroll
            for (int d = 0; d < 4; d++) C[a][b][d] = 0.0f;

    // prologue
    issue(0);
    asm volatile("cp.async.commit_group;" ::: "memory");
    issue(1);
    asm volatile("cp.async.commit_group;" ::: "memory");
    asm volatile("cp.async.wait_group 0;" ::: "memory");
    __syncthreads();                       // lut + packed(0) visible
    float s_h = amrow[1];                  // scale for dequant(1) at iter 0
    dequant(0, amrow[0]);
    issue(2);
    asm volatile("cp.async.commit_group;" ::: "memory");

#pragma unroll 1
    for (int c = 0; c < KCHUNKS; c++) {
        asm volatile("cp.async.wait_group 1;" ::: "memory");
        __syncthreads();   // orders: packed(c+1)/A(c) landed; fp16B(c) STS'd

        if (c + 1 < KCHUNKS) dequant(c + 1, s_h);
        if (c + 3 < KCHUNKS) {
            issue(c + 3);
            asm volatile("cp.async.commit_group;" ::: "memory");
        }
        float s_next = (c + 2 < KCHUNKS) ? amrow[c + 2] : 0.0f;

        const uint32_t sa = sb + (c & 3) * A_ST;
        const uint32_t sB = sb + B16_OFF + (c & 1) * B16_ST;
#pragma unroll
        for (int ks = 0; ks < 4; ks++) {
            uint32_t af[4][4], bf[2][4];
#pragma unroll
            for (int mi = 0; mi < 4; mi++)
                ldm_x4(af[mi], (sa + aoff0 + (uint32_t)(mi << 11) +
                                (uint32_t)(ks << 5)) ^ xorv);
#pragma unroll
            for (int nj = 0; nj < 2; nj++)
                ldm_x4(bf[nj], (sB + boff0 + (uint32_t)(nj << 11) +
                                (uint32_t)(ks << 5)) ^ xorv);
#pragma unroll
            for (int mi = 0; mi < 4; mi++)
#pragma unroll
                for (int nj = 0; nj < 2; nj++) {
                    mma16816(C[mi][2 * nj + 0], af[mi], bf[nj][0], bf[nj][2]);
                    mma16816(C[mi][2 * nj + 1], af[mi], bf[nj][1], bf[nj][3]);
                }
        }
        s_h = s_next;
        // no trailing sync: next iteration's sync precedes any stage reuse
    }

    // epilogue: D frag (mi, nf): rows row0+warp_m*64+mi*16+{g, g+8},
    // cols col0+warp_n*32+nf*8+q*2 (+1)
    const int g = lane >> 2, q = lane & 3;
    const int rbase = row0 + warp_m * 64 + g;
    const int cbase = col0 + warp_n * 32 + q * 2;
    float2 bv[4];
#pragma unroll
    for (int nf = 0; nf < 4; nf++) {
        bv[nf].x = __ldg(bias + cbase + nf * 8);
        bv[nf].y = __ldg(bias + cbase + nf * 8 + 1);
    }
#pragma unroll
    for (int mi = 0; mi < 4; mi++) {
        const int r_lo = rbase + mi * 16;
#pragma unroll
        for (int nf = 0; nf < 4; nf++) {
            const int cc = cbase + nf * 8;
            float2 v0, v1;
            v0.x = C[mi][nf][0] + bv[nf].x;
            v0.y = C[mi][nf][1] + bv[nf].y;
            v1.x = C[mi][nf][2] + bv[nf].x;
            v1.y = C[mi][nf][3] + bv[nf].y;
            *reinterpret_cast<float2*>(out + (size_t)r_lo * OUT_F + cc) = v0;
            *reinterpret_cast<float2*>(out + (size_t)(r_lo + 8) * OUT_F + cc) = v1;
        }
    }
}

// ---------------------------------------------------------------------------
// launch
// ---------------------------------------------------------------------------
extern "C" void kernel_launch(void* const* d_in, const int* in_sizes, int n_in,
                              void* d_out, int out_size) {
    const float* x      = (const float*)d_in[0];
    const int*   packed = (const int*)d_in[1];
    const float* absmax = (const float*)d_in[2];
    const float* bias   = (const float*)d_in[3];
    float* out = (float*)d_out;

    cvt_kernel<<<CVT_BLOCKS, 256>>>(x);

    cudaFuncSetAttribute(gemm_kernel,
                         cudaFuncAttributeMaxDynamicSharedMemorySize, SMEM_BYTES);
    dim3 grid(OUT_F / BN, MROWS / BM);  // (86, 8)
    gemm_kernel<<<grid, 512, SMEM_BYTES>>>(packed, absmax, bias, out);
}

// round 9
// speedup vs baseline: 1.1195x; 1.1195x over previous
#include <cuda_runtime.h>
#include <cuda_fp16.h>
#include <cstdint>

// Problem dims
#define IN_F   4096
#define OUT_F  11008
#define MROWS  2048
#define NUMEL  (IN_F * OUT_F)        // 45,088,768
#define PACKED_N (NUMEL / 2)         // 22,544,384

// GEMM tiling
#define BM 256
#define BN 128
#define BK 64
#define KCHUNKS (IN_F / BK)          // 64
#define NST 4
#define A_BYTES (BM * 128)           // 32768 (256 rows x 128B)
#define B_BYTES (BN * 128)           // 16384
#define STAGE_BYTES (A_BYTES + B_BYTES)   // 49152
#define SMEM_BYTES (NST * STAGE_BYTES)    // 196608

// prep kernel split
#define CVT_BLOCKS ((MROWS * IN_F / 4) / 256)   // 8192
#define DEQ_BLOCKS ((PACKED_N / 4) / 256)       // 22016

// Scratch (device globals; no allocation allowed)
__device__ __half g_W[NUMEL];          // dequantized W, row-major [OUT_F][IN_F]
__device__ __half g_X[MROWS * IN_F];   // fp16 x

__constant__ float c_nf4[16] = {
    -1.0f, -0.6961928009986877f, -0.5250730514526367f, -0.39491748809814453f,
    -0.28444138169288635f, -0.18477343022823334f, -0.09105003625154495f, 0.0f,
    0.07958029955625534f, 0.16093020141124725f, 0.24611230194568634f,
    0.33791524171829224f, 0.44070982933044434f, 0.5626170039176941f,
    0.7229568362236023f, 1.0f};

// ---------------------------------------------------------------------------
// fused prep: blocks [0, CVT_BLOCKS) convert x fp32->fp16,
//             blocks [CVT_BLOCKS, ...) dequant NF4 -> fp16 W.
// Dequant via 32x-replicated smem LUT (bank == lane, conflict-free; round 6
// measured: prep ~35us incl cvt).
// ---------------------------------------------------------------------------
__global__ void prep_kernel(const float* __restrict__ x,
                            const int* __restrict__ packed,
                            const float* __restrict__ absmax) {
    __shared__ float lut[16 * 32];
    const int b = blockIdx.x;
    const int tid = threadIdx.x;
    if (b < CVT_BLOCKS) {
        int i = b * 256 + tid;                            // handles 4 floats
        float4 v = reinterpret_cast<const float4*>(x)[i];
        __half2* o = reinterpret_cast<__half2*>(g_X);
        o[2 * i]     = __floats2half2_rn(v.x, v.y);
        o[2 * i + 1] = __floats2half2_rn(v.z, v.w);
    } else {
        lut[tid]       = c_nf4[tid >> 5];                 // uniform index
        lut[tid + 256] = c_nf4[(tid + 256) >> 5];
        __syncthreads();
        const int lane = tid & 31;
        int i = (b - CVT_BLOCKS) * 256 + tid;             // packed[4i..4i+3]
        int4 pk = reinterpret_cast<const int4*>(packed)[i];
        float s = absmax[i >> 3];                          // (4i)/32 == i/8
        int v[4] = {pk.x, pk.y, pk.z, pk.w};
        __half h[8];
#pragma unroll
        for (int j = 0; j < 4; j++) {
            float whi = lut[((v[j] >> 4) & 0xF) * 32 + lane];
            float wlo = lut[(v[j] & 0xF) * 32 + lane];
            h[2 * j]     = __float2half_rn(whi * s);
            h[2 * j + 1] = __float2half_rn(wlo * s);
        }
        reinterpret_cast<uint4*>(g_W)[i] = *reinterpret_cast<uint4*>(h);
    }
}

// ---------------------------------------------------------------------------
// PTX helpers
// ---------------------------------------------------------------------------
__device__ __forceinline__ uint32_t smem_u32(const void* p) {
    uint32_t a;
    asm("{ .reg .u64 t; cvta.to.shared.u64 t, %1; cvt.u32.u64 %0, t; }"
        : "=r"(a) : "l"(p));
    return a;
}

__device__ __forceinline__ void cp16(uint32_t saddr, const void* gaddr) {
    asm volatile("cp.async.cg.shared.global [%0], [%1], 16;"
                 :: "r"(saddr), "l"(gaddr));
}

__device__ __forceinline__ void ldm_x4(uint32_t* r, uint32_t addr) {
    asm volatile("ldmatrix.sync.aligned.m8n8.x4.shared.b16 {%0,%1,%2,%3}, [%4];"
                 : "=r"(r[0]), "=r"(r[1]), "=r"(r[2]), "=r"(r[3]) : "r"(addr));
}

__device__ __forceinline__ void mma16816(float* c, const uint32_t* a,
                                         uint32_t b0, uint32_t b1) {
    asm volatile(
        "mma.sync.aligned.m16n8k16.row.col.f32.f16.f16.f32 "
        "{%0,%1,%2,%3}, {%4,%5,%6,%7}, {%8,%9}, {%0,%1,%2,%3};"
        : "+f"(c[0]), "+f"(c[1]), "+f"(c[2]), "+f"(c[3])
        : "r"(a[0]), "r"(a[1]), "r"(a[2]), "r"(a[3]), "r"(b0), "r"(b1));
}

// ---------------------------------------------------------------------------
// GEMM: out[256,128] tile = A[256,K] * B[128,K]^T + bias, fp16 in / fp32 acc.
// 256 threads = 8 warps in 4(m) x 2(n); warp tile 64x64. 4-stage cp.async
// ring, prefetch distance 2, one __syncthreads per chunk. NEW: ldmatrix
// fragments are double-buffered so HMMA issue of k-step ks overlaps the
// LDSM of ks+1 (attacks the measured 16cyc-issue/8cyc-pipe HMMA gap).
// ---------------------------------------------------------------------------
__global__ void __launch_bounds__(256, 1)
gemm_kernel(const float* __restrict__ bias, float* __restrict__ out) {
    extern __shared__ char smem[];
    const uint32_t sb = smem_u32(smem);
    const int tid = threadIdx.x;
    const int wid = tid >> 5;
    const int lane = tid & 31;
    const int warp_m = wid >> 1;          // 0..3
    const int warp_n = wid & 1;           // 0..1
    const int row0 = blockIdx.y * BM;
    const int col0 = blockIdx.x * BN;

    const __half* Ab = g_X + (size_t)row0 * IN_F;
    const __half* Bb = g_W + (size_t)col0 * IN_F;

    // cp.async of chunk c into stage c%4
    auto issue = [&](int c) {
        const int s = c & (NST - 1);
        const int kc = c * BK;
        const uint32_t base = sb + s * STAGE_BYTES;
#pragma unroll
        for (int i = 0; i < 8; i++) {     // A: 2048 16B units / 256 thr
            int u = tid + (i << 8);
            int r = u >> 3, sg = u & 7;
            uint32_t bo = (uint32_t)((r << 7) + (sg << 4));
            uint32_t sw = bo ^ ((bo >> 3) & 0x70);
            cp16(base + sw, Ab + (size_t)r * IN_F + kc + sg * 8);
        }
#pragma unroll
        for (int i = 0; i < 4; i++) {     // B: 1024 units / 256 thr
            int u = tid + (i << 8);
            int r = u >> 3, sg = u & 7;
            uint32_t bo = (uint32_t)((r << 7) + (sg << 4));
            uint32_t sw = bo ^ ((bo >> 3) & 0x70);
            cp16(base + A_BYTES + sw, Bb + (size_t)r * IN_F + kc + sg * 8);
        }
    };

    // per-thread ldmatrix lane addressing (SW128; validated round 2)
    const int grp = lane >> 3, lr = lane & 7;
    const uint32_t xorv = (uint32_t)(lr << 4);
    const uint32_t laneoff =
        (uint32_t)((((grp & 1) << 3) + lr) << 7) + (uint32_t)((grp >> 1) << 4);
    const uint32_t aoff0 = (uint32_t)((warp_m * 64) << 7) + laneoff;
    const uint32_t boff0 = (uint32_t)((warp_n * 64) << 7) + laneoff;

    float C[4][8][4];
#pragma unroll
    for (int a = 0; a < 4; a++)
#pragma unroll
        for (int b = 0; b < 8; b++)
#pragma unroll
            for (int d = 0; d < 4; d++) C[a][b][d] = 0.0f;

    // double-buffered fragments
    uint32_t af[2][4][4], bf[2][4][4];
    auto load_frags = [&](uint32_t sa, uint32_t sB, int ks, int buf) {
#pragma unroll
        for (int mi = 0; mi < 4; mi++)
            ldm_x4(af[buf][mi], (sa + aoff0 + (uint32_t)(mi << 11) +
                                 (uint32_t)(ks << 5)) ^ xorv);
#pragma unroll
        for (int nj = 0; nj < 4; nj++)
            ldm_x4(bf[buf][nj], (sB + boff0 + (uint32_t)(nj << 11) +
                                 (uint32_t)(ks << 5)) ^ xorv);
    };

    // prologue: 2 chunks in flight
    issue(0);
    asm volatile("cp.async.commit_group;" ::: "memory");
    issue(1);
    asm volatile("cp.async.commit_group;" ::: "memory");

#pragma unroll 1
    for (int c = 0; c < KCHUNKS; c++) {
        asm volatile("cp.async.wait_group 1;" ::: "memory");
        __syncthreads();

        if (c + 2 < KCHUNKS) issue(c + 2);
        asm volatile("cp.async.commit_group;" ::: "memory");

        const uint32_t sa = sb + (c & (NST - 1)) * STAGE_BYTES;
        const uint32_t sB = sa + A_BYTES;

        load_frags(sa, sB, 0, 0);
#pragma unroll
        for (int ks = 0; ks < 4; ks++) {
            const int cur = ks & 1, nxt = cur ^ 1;
            if (ks < 3) load_frags(sa, sB, ks + 1, nxt);
#pragma unroll
            for (int mi = 0; mi < 4; mi++)
#pragma unroll
                for (int nj = 0; nj < 4; nj++) {
                    mma16816(C[mi][2 * nj + 0], af[cur][mi],
                             bf[cur][nj][0], bf[cur][nj][2]);
                    mma16816(C[mi][2 * nj + 1], af[cur][mi],
                             bf[cur][nj][1], bf[cur][nj][3]);
                }
        }
        // no trailing sync: next iteration's sync precedes any stage reuse
    }

    // epilogue: D frag (mi, nf): rows row0+warp_m*64+mi*16+{g, g+8},
    // cols col0+warp_n*64+nf*8+q*2 (+1)
    const int g = lane >> 2, q = lane & 3;
    const int rbase = row0 + warp_m * 64 + g;
    const int cbase = col0 + warp_n * 64 + q * 2;
    float2 bv[8];
#pragma unroll
    for (int nf = 0; nf < 8; nf++) {
        bv[nf].x = __ldg(bias + cbase + nf * 8);
        bv[nf].y = __ldg(bias + cbase + nf * 8 + 1);
    }
#pragma unroll
    for (int mi = 0; mi < 4; mi++) {
        const int r_lo = rbase + mi * 16;
#pragma unroll
        for (int nf = 0; nf < 8; nf++) {
            const int cc = cbase + nf * 8;
            float2 v0, v1;
            v0.x = C[mi][nf][0] + bv[nf].x;
            v0.y = C[mi][nf][1] + bv[nf].y;
            v1.x = C[mi][nf][2] + bv[nf].x;
            v1.y = C[mi][nf][3] + bv[nf].y;
            *reinterpret_cast<float2*>(out + (size_t)r_lo * OUT_F + cc) = v0;
            *reinterpret_cast<float2*>(out + (size_t)(r_lo + 8) * OUT_F + cc) = v1;
        }
    }
}

// ---------------------------------------------------------------------------
// launch
// ---------------------------------------------------------------------------
extern "C" void kernel_launch(void* const* d_in, const int* in_sizes, int n_in,
                              void* d_out, int out_size) {
    const float* x      = (const float*)d_in[0];
    const int*   packed = (const int*)d_in[1];
    const float* absmax = (const float*)d_in[2];
    const float* bias   = (const float*)d_in[3];
    float* out = (float*)d_out;

    prep_kernel<<<CVT_BLOCKS + DEQ_BLOCKS, 256>>>(x, packed, absmax);

    cudaFuncSetAttribute(gemm_kernel,
                         cudaFuncAttributeMaxDynamicSharedMemorySize, SMEM_BYTES);
    dim3 grid(OUT_F / BN, MROWS / BM);  // (86, 8)
    gemm_kernel<<<grid, 256, SMEM_BYTES>>>(bias, out);
}

// round 10
// speedup vs baseline: 1.1632x; 1.0391x over previous
#include <cuda_runtime.h>
#include <cuda_fp16.h>
#include <cstdint>

// Problem dims
#define IN_F   4096
#define OUT_F  11008
#define MROWS  2048
#define NUMEL  (IN_F * OUT_F)        // 45,088,768
#define PACKED_N (NUMEL / 2)         // 22,544,384

// GEMM tiling: 128x128 CTA tile, 4 warps (2x2), warp tile 64x64, 2 CTAs/SM
#define BM 128
#define BN 128
#define BK 64
#define KCHUNKS (IN_F / BK)          // 64
#define NST 3
#define A_BYTES (BM * 128)           // 16384
#define B_BYTES (BN * 128)           // 16384
#define STAGE_BYTES (A_BYTES + B_BYTES)   // 32768
#define SMEM_BYTES (NST * STAGE_BYTES)    // 98304 (x2 CTAs = 196608 <= 228KB)

// prep kernel split
#define CVT_BLOCKS ((MROWS * IN_F / 4) / 256)   // 8192
#define DEQ_BLOCKS ((PACKED_N / 4) / 256)       // 22016

// Scratch (device globals; no allocation allowed)
__device__ __half g_W[NUMEL];          // dequantized W, row-major [OUT_F][IN_F]
__device__ __half g_X[MROWS * IN_F];   // fp16 x

__constant__ float c_nf4[16] = {
    -1.0f, -0.6961928009986877f, -0.5250730514526367f, -0.39491748809814453f,
    -0.28444138169288635f, -0.18477343022823334f, -0.09105003625154495f, 0.0f,
    0.07958029955625534f, 0.16093020141124725f, 0.24611230194568634f,
    0.33791524171829224f, 0.44070982933044434f, 0.5626170039176941f,
    0.7229568362236023f, 1.0f};

// ---------------------------------------------------------------------------
// fused prep: blocks [0, CVT_BLOCKS) convert x fp32->fp16,
//             blocks [CVT_BLOCKS, ...) dequant NF4 -> fp16 W via
//             32x-replicated conflict-free smem LUT (round 6: ~35us total)
// ---------------------------------------------------------------------------
__global__ void prep_kernel(const float* __restrict__ x,
                            const int* __restrict__ packed,
                            const float* __restrict__ absmax) {
    __shared__ float lut[16 * 32];
    const int b = blockIdx.x;
    const int tid = threadIdx.x;
    if (b < CVT_BLOCKS) {
        int i = b * 256 + tid;                            // handles 4 floats
        float4 v = reinterpret_cast<const float4*>(x)[i];
        __half2* o = reinterpret_cast<__half2*>(g_X);
        o[2 * i]     = __floats2half2_rn(v.x, v.y);
        o[2 * i + 1] = __floats2half2_rn(v.z, v.w);
    } else {
        lut[tid]       = c_nf4[tid >> 5];                 // uniform index
        lut[tid + 256] = c_nf4[(tid + 256) >> 5];
        __syncthreads();
        const int lane = tid & 31;
        int i = (b - CVT_BLOCKS) * 256 + tid;             // packed[4i..4i+3]
        int4 pk = reinterpret_cast<const int4*>(packed)[i];
        float s = absmax[i >> 3];                          // (4i)/32 == i/8
        int v[4] = {pk.x, pk.y, pk.z, pk.w};
        __half h[8];
#pragma unroll
        for (int j = 0; j < 4; j++) {
            float whi = lut[((v[j] >> 4) & 0xF) * 32 + lane];
            float wlo = lut[(v[j] & 0xF) * 32 + lane];
            h[2 * j]     = __float2half_rn(whi * s);
            h[2 * j + 1] = __float2half_rn(wlo * s);
        }
        reinterpret_cast<uint4*>(g_W)[i] = *reinterpret_cast<uint4*>(h);
    }
}

// ---------------------------------------------------------------------------
// PTX helpers
// ---------------------------------------------------------------------------
__device__ __forceinline__ uint32_t smem_u32(const void* p) {
    uint32_t a;
    asm("{ .reg .u64 t; cvta.to.shared.u64 t, %1; cvt.u32.u64 %0, t; }"
        : "=r"(a) : "l"(p));
    return a;
}

__device__ __forceinline__ void cp16(uint32_t saddr, const void* gaddr) {
    asm volatile("cp.async.cg.shared.global [%0], [%1], 16;"
                 :: "r"(saddr), "l"(gaddr));
}

__device__ __forceinline__ void ldm_x4(uint32_t* r, uint32_t addr) {
    asm volatile("ldmatrix.sync.aligned.m8n8.x4.shared.b16 {%0,%1,%2,%3}, [%4];"
                 : "=r"(r[0]), "=r"(r[1]), "=r"(r[2]), "=r"(r[3]) : "r"(addr));
}

__device__ __forceinline__ void mma16816(float* c, const uint32_t* a,
                                         uint32_t b0, uint32_t b1) {
    asm volatile(
        "mma.sync.aligned.m16n8k16.row.col.f32.f16.f16.f32 "
        "{%0,%1,%2,%3}, {%4,%5,%6,%7}, {%8,%9}, {%0,%1,%2,%3};"
        : "+f"(c[0]), "+f"(c[1]), "+f"(c[2]), "+f"(c[3])
        : "r"(a[0]), "r"(a[1]), "r"(a[2]), "r"(a[3]), "r"(b0), "r"(b1));
}

// ---------------------------------------------------------------------------
// GEMM: out[128,128] tile = A[128,K] * B[128,K]^T + bias, fp16 in / fp32 acc.
// 128 threads = 4 warps in 2(m) x 2(n); warp tile 64x64 (round-9 winner's
// per-warp structure incl. double-buffered ldmatrix fragments). NEW: 2 CTAs
// per SM (launch_bounds(128,2), 98KB smem/CTA) so each SMSP hosts 2 warps
// from INDEPENDENT CTAs — one CTA's __syncthreads / cp.async-wait / chunk-
// prologue LDSM bubbles are covered by the other CTA's HMMA stream.
// 3-stage cp.async ring, prefetch distance 2, one sync per chunk.
// ---------------------------------------------------------------------------
__global__ void __launch_bounds__(128, 2)
gemm_kernel(const float* __restrict__ bias, float* __restrict__ out) {
    extern __shared__ char smem[];
    const uint32_t sb = smem_u32(smem);
    const int tid = threadIdx.x;
    const int wid = tid >> 5;
    const int lane = tid & 31;
    const int warp_m = wid >> 1;          // 0..1
    const int warp_n = wid & 1;           // 0..1
    const int row0 = blockIdx.y * BM;
    const int col0 = blockIdx.x * BN;

    const __half* Ab = g_X + (size_t)row0 * IN_F;
    const __half* Bb = g_W + (size_t)col0 * IN_F;

    // cp.async of chunk c into stage c%3 (128 thr: 8 A + 8 B units each)
    auto issue = [&](int c) {
        const int s = c % NST;
        const int kc = c * BK;
        const uint32_t base = sb + s * STAGE_BYTES;
#pragma unroll
        for (int i = 0; i < 8; i++) {     // A: 1024 16B units / 128 thr
            int u = tid + (i << 7);
            int r = u >> 3, sg = u & 7;
            uint32_t bo = (uint32_t)((r << 7) + (sg << 4));
            uint32_t sw = bo ^ ((bo >> 3) & 0x70);
            cp16(base + sw, Ab + (size_t)r * IN_F + kc + sg * 8);
            cp16(base + A_BYTES + sw, Bb + (size_t)r * IN_F + kc + sg * 8);
        }
    };

    // per-thread ldmatrix lane addressing (SW128; validated round 2)
    const int grp = lane >> 3, lr = lane & 7;
    const uint32_t xorv = (uint32_t)(lr << 4);
    const uint32_t laneoff =
        (uint32_t)((((grp & 1) << 3) + lr) << 7) + (uint32_t)((grp >> 1) << 4);
    const uint32_t aoff0 = (uint32_t)((warp_m * 64) << 7) + laneoff;
    const uint32_t boff0 = (uint32_t)((warp_n * 64) << 7) + laneoff;

    float C[4][8][4];
#pragma unroll
    for (int a = 0; a < 4; a++)
#pragma unroll
        for (int b = 0; b < 8; b++)
#pragma unroll
            for (int d = 0; d < 4; d++) C[a][b][d] = 0.0f;

    // double-buffered fragments
    uint32_t af[2][4][4], bf[2][4][4];
    auto load_frags = [&](uint32_t sa, uint32_t sB, int ks, int buf) {
#pragma unroll
        for (int mi = 0; mi < 4; mi++)
            ldm_x4(af[buf][mi], (sa + aoff0 + (uint32_t)(mi << 11) +
                                 (uint32_t)(ks << 5)) ^ xorv);
#pragma unroll
        for (int nj = 0; nj < 4; nj++)
            ldm_x4(bf[buf][nj], (sB + boff0 + (uint32_t)(nj << 11) +
                                 (uint32_t)(ks << 5)) ^ xorv);
    };

    // prologue: 2 chunks in flight
    issue(0);
    asm volatile("cp.async.commit_group;" ::: "memory");
    issue(1);
    asm volatile("cp.async.commit_group;" ::: "memory");

#pragma unroll 1
    for (int c = 0; c < KCHUNKS; c++) {
        asm volatile("cp.async.wait_group 1;" ::: "memory");
        __syncthreads();

        const uint32_t sa = sb + (c % NST) * STAGE_BYTES;
        const uint32_t sB = sa + A_BYTES;

        // MMA-critical LDSM first, then the prefetch burst
        load_frags(sa, sB, 0, 0);
        if (c + 2 < KCHUNKS) issue(c + 2);
        asm volatile("cp.async.commit_group;" ::: "memory");

#pragma unroll
        for (int ks = 0; ks < 4; ks++) {
            const int cur = ks & 1, nxt = cur ^ 1;
            if (ks < 3) load_frags(sa, sB, ks + 1, nxt);
#pragma unroll
            for (int mi = 0; mi < 4; mi++)
#pragma unroll
                for (int nj = 0; nj < 4; nj++) {
                    mma16816(C[mi][2 * nj + 0], af[cur][mi],
                             bf[cur][nj][0], bf[cur][nj][2]);
                    mma16816(C[mi][2 * nj + 1], af[cur][mi],
                             bf[cur][nj][1], bf[cur][nj][3]);
                }
        }
        __syncthreads();   // NST=3 with distance 2: protect stage reuse
    }

    // epilogue: D frag (mi, nf): rows row0+warp_m*64+mi*16+{g, g+8},
    // cols col0+warp_n*64+nf*8+q*2 (+1)
    const int g = lane >> 2, q = lane & 3;
    const int rbase = row0 + warp_m * 64 + g;
    const int cbase = col0 + warp_n * 64 + q * 2;
    float2 bv[8];
#pragma unroll
    for (int nf = 0; nf < 8; nf++) {
        bv[nf].x = __ldg(bias + cbase + nf * 8);
        bv[nf].y = __ldg(bias + cbase + nf * 8 + 1);
    }
#pragma unroll
    for (int mi = 0; mi < 4; mi++) {
        const int r_lo = rbase + mi * 16;
#pragma unroll
        for (int nf = 0; nf < 8; nf++) {
            const int cc = cbase + nf * 8;
            float2 v0, v1;
            v0.x = C[mi][nf][0] + bv[nf].x;
            v0.y = C[mi][nf][1] + bv[nf].y;
            v1.x = C[mi][nf][2] + bv[nf].x;
            v1.y = C[mi][nf][3] + bv[nf].y;
            *reinterpret_cast<float2*>(out + (size_t)r_lo * OUT_F + cc) = v0;
            *reinterpret_cast<float2*>(out + (size_t)(r_lo + 8) * OUT_F + cc) = v1;
        }
    }
}

// ---------------------------------------------------------------------------
// launch
// ---------------------------------------------------------------------------
extern "C" void kernel_launch(void* const* d_in, const int* in_sizes, int n_in,
                              void* d_out, int out_size) {
    const float* x      = (const float*)d_in[0];
    const int*   packed = (const int*)d_in[1];
    const float* absmax = (const float*)d_in[2];
    const float* bias   = (const float*)d_in[3];
    float* out = (float*)d_out;

    prep_kernel<<<CVT_BLOCKS + DEQ_BLOCKS, 256>>>(x, packed, absmax);

    cudaFuncSetAttribute(gemm_kernel,
                         cudaFuncAttributeMaxDynamicSharedMemorySize, SMEM_BYTES);
    dim3 grid(OUT_F / BN, MROWS / BM);  // (86, 16)
    gemm_kernel<<<grid, 128, SMEM_BYTES>>>(bias, out);
}

// round 11
// speedup vs baseline: 1.1991x; 1.0308x over previous
#include <cuda_runtime.h>
#include <cuda_fp16.h>
#include <cstdint>

// Problem dims
#define IN_F   4096
#define OUT_F  11008
#define MROWS  2048
#define NUMEL  (IN_F * OUT_F)        // 45,088,768
#define PACKED_N (NUMEL / 2)         // 22,544,384

// GEMM tiling: 128x128 CTA tile, 4 warps (2x2), warp tile 64x64, 2 CTAs/SM
#define BM 128
#define BN 128
#define BK 64
#define KCHUNKS (IN_F / BK)          // 64
#define NST 3
#define A_BYTES (BM * 128)           // 16384
#define B_BYTES (BN * 128)           // 16384
#define STAGE_BYTES (A_BYTES + B_BYTES)   // 32768
#define SMEM_BYTES (NST * STAGE_BYTES)    // 98304 (x2 CTAs = 196608 <= 228KB)

// prep kernel split
#define CVT_BLOCKS ((MROWS * IN_F / 4) / 256)   // 8192
#define DEQ_BLOCKS ((PACKED_N / 4) / 256)       // 22016

// Scratch (device globals; no allocation allowed)
__device__ __half g_W[NUMEL];          // dequantized W, row-major [OUT_F][IN_F]
__device__ __half g_X[MROWS * IN_F];   // fp16 x

__constant__ float c_nf4[16] = {
    -1.0f, -0.6961928009986877f, -0.5250730514526367f, -0.39491748809814453f,
    -0.28444138169288635f, -0.18477343022823334f, -0.09105003625154495f, 0.0f,
    0.07958029955625534f, 0.16093020141124725f, 0.24611230194568634f,
    0.33791524171829224f, 0.44070982933044434f, 0.5626170039176941f,
    0.7229568362236023f, 1.0f};

// ---------------------------------------------------------------------------
// fused prep: blocks [0, CVT_BLOCKS) convert x fp32->fp16,
//             blocks [CVT_BLOCKS, ...) dequant NF4 -> fp16 W via
//             32x-replicated conflict-free smem LUT (round 6: ~35us, at the
//             228MB DRAM floor)
// ---------------------------------------------------------------------------
__global__ void prep_kernel(const float* __restrict__ x,
                            const int* __restrict__ packed,
                            const float* __restrict__ absmax) {
    __shared__ float lut[16 * 32];
    const int b = blockIdx.x;
    const int tid = threadIdx.x;
    if (b < CVT_BLOCKS) {
        int i = b * 256 + tid;                            // handles 4 floats
        float4 v = reinterpret_cast<const float4*>(x)[i];
        __half2* o = reinterpret_cast<__half2*>(g_X);
        o[2 * i]     = __floats2half2_rn(v.x, v.y);
        o[2 * i + 1] = __floats2half2_rn(v.z, v.w);
    } else {
        lut[tid]       = c_nf4[tid >> 5];                 // uniform index
        lut[tid + 256] = c_nf4[(tid + 256) >> 5];
        __syncthreads();
        const int lane = tid & 31;
        int i = (b - CVT_BLOCKS) * 256 + tid;             // packed[4i..4i+3]
        int4 pk = reinterpret_cast<const int4*>(packed)[i];
        float s = absmax[i >> 3];                          // (4i)/32 == i/8
        int v[4] = {pk.x, pk.y, pk.z, pk.w};
        __half h[8];
#pragma unroll
        for (int j = 0; j < 4; j++) {
            float whi = lut[((v[j] >> 4) & 0xF) * 32 + lane];
            float wlo = lut[(v[j] & 0xF) * 32 + lane];
            h[2 * j]     = __float2half_rn(whi * s);
            h[2 * j + 1] = __float2half_rn(wlo * s);
        }
        reinterpret_cast<uint4*>(g_W)[i] = *reinterpret_cast<uint4*>(h);
    }
}

// ---------------------------------------------------------------------------
// PTX helpers
// ---------------------------------------------------------------------------
__device__ __forceinline__ uint32_t smem_u32(const void* p) {
    uint32_t a;
    asm("{ .reg .u64 t; cvta.to.shared.u64 t, %1; cvt.u32.u64 %0, t; }"
        : "=r"(a) : "l"(p));
    return a;
}

__device__ __forceinline__ void cp16(uint32_t saddr, const void* gaddr) {
    asm volatile("cp.async.cg.shared.global [%0], [%1], 16;"
                 :: "r"(saddr), "l"(gaddr));
}

__device__ __forceinline__ void ldm_x4(uint32_t* r, uint32_t addr) {
    asm volatile("ldmatrix.sync.aligned.m8n8.x4.shared.b16 {%0,%1,%2,%3}, [%4];"
                 : "=r"(r[0]), "=r"(r[1]), "=r"(r[2]), "=r"(r[3]) : "r"(addr));
}

__device__ __forceinline__ void mma16816(float* c, const uint32_t* a,
                                         uint32_t b0, uint32_t b1) {
    asm volatile(
        "mma.sync.aligned.m16n8k16.row.col.f32.f16.f16.f32 "
        "{%0,%1,%2,%3}, {%4,%5,%6,%7}, {%8,%9}, {%0,%1,%2,%3};"
        : "+f"(c[0]), "+f"(c[1]), "+f"(c[2]), "+f"(c[3])
        : "r"(a[0]), "r"(a[1]), "r"(a[2]), "r"(a[3]), "r"(b0), "r"(b1));
}

// ---------------------------------------------------------------------------
// GEMM: out[128,128] tile = A[128,K] * B[128,K]^T + bias, fp16 in / fp32 acc.
// 128 threads = 4 warps in 2(m) x 2(n); warp tile 64x64, double-buffered
// ldmatrix fragments, 2 CTAs/SM (independent barriers cover each other's
// bubbles). 3-stage cp.async ring, prefetch distance 2.
// Round-11 changes: the trailing per-chunk __syncthreads is removed — the
// top-of-iteration sync already orders all warps past their iter-(c-1) LDSMs
// before issue(c+2) overwrites stage (c-1)%3. Stage index via wrap counter.
// ---------------------------------------------------------------------------
__global__ void __launch_bounds__(128, 2)
gemm_kernel(const float* __restrict__ bias, float* __restrict__ out) {
    extern __shared__ char smem[];
    const uint32_t sb = smem_u32(smem);
    const int tid = threadIdx.x;
    const int wid = tid >> 5;
    const int lane = tid & 31;
    const int warp_m = wid >> 1;          // 0..1
    const int warp_n = wid & 1;           // 0..1
    const int row0 = blockIdx.y * BM;
    const int col0 = blockIdx.x * BN;

    const __half* Ab = g_X + (size_t)row0 * IN_F;
    const __half* Bb = g_W + (size_t)col0 * IN_F;

    // cp.async of chunk c into stage s (128 thr: 8 A + 8 B units each)
    auto issue = [&](int c, int s) {
        const int kc = c * BK;
        const uint32_t base = sb + s * STAGE_BYTES;
#pragma unroll
        for (int i = 0; i < 8; i++) {     // 1024 16B units per tile / 128 thr
            int u = tid + (i << 7);
            int r = u >> 3, sg = u & 7;
            uint32_t bo = (uint32_t)((r << 7) + (sg << 4));
            uint32_t sw = bo ^ ((bo >> 3) & 0x70);
            cp16(base + sw, Ab + (size_t)r * IN_F + kc + sg * 8);
            cp16(base + A_BYTES + sw, Bb + (size_t)r * IN_F + kc + sg * 8);
        }
    };

    // per-thread ldmatrix lane addressing (SW128; validated round 2)
    const int grp = lane >> 3, lr = lane & 7;
    const uint32_t xorv = (uint32_t)(lr << 4);
    const uint32_t laneoff =
        (uint32_t)((((grp & 1) << 3) + lr) << 7) + (uint32_t)((grp >> 1) << 4);
    const uint32_t aoff0 = (uint32_t)((warp_m * 64) << 7) + laneoff;
    const uint32_t boff0 = (uint32_t)((warp_n * 64) << 7) + laneoff;

    float C[4][8][4];
#pragma unroll
    for (int a = 0; a < 4; a++)
#pragma unroll
        for (int b = 0; b < 8; b++)
#pragma unroll
            for (int d = 0; d < 4; d++) C[a][b][d] = 0.0f;

    // double-buffered fragments
    uint32_t af[2][4][4], bf[2][4][4];
    auto load_frags = [&](uint32_t sa, uint32_t sB, int ks, int buf) {
#pragma unroll
        for (int mi = 0; mi < 4; mi++)
            ldm_x4(af[buf][mi], (sa + aoff0 + (uint32_t)(mi << 11) +
                                 (uint32_t)(ks << 5)) ^ xorv);
#pragma unroll
        for (int nj = 0; nj < 4; nj++)
            ldm_x4(bf[buf][nj], (sB + boff0 + (uint32_t)(nj << 11) +
                                 (uint32_t)(ks << 5)) ^ xorv);
    };

    // prologue: 2 chunks in flight
    issue(0, 0);
    asm volatile("cp.async.commit_group;" ::: "memory");
    issue(1, 1);
    asm volatile("cp.async.commit_group;" ::: "memory");

    int s_cur = 0;     // stage of chunk c
    int s_pre = 2;     // stage for chunk c+2
#pragma unroll 1
    for (int c = 0; c < KCHUNKS; c++) {
        asm volatile("cp.async.wait_group 1;" ::: "memory");
        __syncthreads();   // chunk c landed; all warps done with iter c-1 LDSM

        const uint32_t sa = sb + s_cur * STAGE_BYTES;
        const uint32_t sB = sa + A_BYTES;

        // MMA-critical LDSM first, then the prefetch burst
        load_frags(sa, sB, 0, 0);
        if (c + 2 < KCHUNKS) issue(c + 2, s_pre);
        asm volatile("cp.async.commit_group;" ::: "memory");

#pragma unroll
        for (int ks = 0; ks < 4; ks++) {
            const int cur = ks & 1, nxt = cur ^ 1;
            if (ks < 3) load_frags(sa, sB, ks + 1, nxt);
#pragma unroll
            for (int mi = 0; mi < 4; mi++)
#pragma unroll
                for (int nj = 0; nj < 4; nj++) {
                    mma16816(C[mi][2 * nj + 0], af[cur][mi],
                             bf[cur][nj][0], bf[cur][nj][2]);
                    mma16816(C[mi][2 * nj + 1], af[cur][mi],
                             bf[cur][nj][1], bf[cur][nj][3]);
                }
        }
        // stage counters: wrap without %
        s_cur = (s_cur == NST - 1) ? 0 : s_cur + 1;
        s_pre = (s_pre == NST - 1) ? 0 : s_pre + 1;
        // no trailing sync: next iteration's top sync precedes stage reuse
    }

    // epilogue: D frag (mi, nf): rows row0+warp_m*64+mi*16+{g, g+8},
    // cols col0+warp_n*64+nf*8+q*2 (+1)
    const int g = lane >> 2, q = lane & 3;
    const int rbase = row0 + warp_m * 64 + g;
    const int cbase = col0 + warp_n * 64 + q * 2;
    float2 bv[8];
#pragma unroll
    for (int nf = 0; nf < 8; nf++) {
        bv[nf].x = __ldg(bias + cbase + nf * 8);
        bv[nf].y = __ldg(bias + cbase + nf * 8 + 1);
    }
#pragma unroll
    for (int mi = 0; mi < 4; mi++) {
        const int r_lo = rbase + mi * 16;
#pragma unroll
        for (int nf = 0; nf < 8; nf++) {
            const int cc = cbase + nf * 8;
            float2 v0, v1;
            v0.x = C[mi][nf][0] + bv[nf].x;
            v0.y = C[mi][nf][1] + bv[nf].y;
            v1.x = C[mi][nf][2] + bv[nf].x;
            v1.y = C[mi][nf][3] + bv[nf].y;
            *reinterpret_cast<float2*>(out + (size_t)r_lo * OUT_F + cc) = v0;
            *reinterpret_cast<float2*>(out + (size_t)(r_lo + 8) * OUT_F + cc) = v1;
        }
    }
}

// ---------------------------------------------------------------------------
// launch
// ---------------------------------------------------------------------------
extern "C" void kernel_launch(void* const* d_in, const int* in_sizes, int n_in,
                              void* d_out, int out_size) {
    const float* x      = (const float*)d_in[0];
    const int*   packed = (const int*)d_in[1];
    const float* absmax = (const float*)d_in[2];
    const float* bias   = (const float*)d_in[3];
    float* out = (float*)d_out;

    prep_kernel<<<CVT_BLOCKS + DEQ_BLOCKS, 256>>>(x, packed, absmax);

    cudaFuncSetAttribute(gemm_kernel,
                         cudaFuncAttributeMaxDynamicSharedMemorySize, SMEM_BYTES);
    dim3 grid(OUT_F / BN, MROWS / BM);  // (86, 16)
    gemm_kernel<<<grid, 128, SMEM_BYTES>>>(bias, out);
}